// round 14
// baseline (speedup 1.0000x reference)
#include <cuda_runtime.h>
#include <cuda_fp16.h>
#include <math.h>
#include <stdint.h>

#define NU 100000
#define NN 20000
#define NT 120000
#define CC 128
#define EE 250000
#define NLAYER 2
#define NKV 220000   // NU + NN + NU
#define SA 136       // smem row stride in halves
#define NDST (NN + 2 * NU)   // (relation,dst) nodes: r0=NN, r1=NU, r2=NU
#define SCAN_BLK 4096
#define SCAN_NB ((NDST + SCAN_BLK - 1) / SCAN_BLK)

// ---------------- scratch (device globals; no allocations allowed) ----------
__device__ __half g_x1h[NT * CC];      // layer-0 output, fp16
__device__ __half g_qh[NT * CC];
__device__ __half g_krelh[NKV * CC];
__device__ __half g_vrelh[NKV * CC];
__device__ __half g_aggrh[NKV * CC];   // normalized per-relation agg (fp16)
__device__ float g_Weff[12 * CC * CC];
__device__ float g_beff[12 * CC];
__device__ __half g_Wh[20 * CC * CC];  // fp16, transposed [n][k]
// CSR scratch
__device__ int g_cnt[NDST];
__device__ int g_offAll[NDST + 1];
__device__ int g_bsum[SCAN_NB];
__device__ int g_srt[3 * EE];

__device__ __forceinline__ float gelu_exact(float x) {
    return 0.5f * x * (1.0f + erff(x * 0.70710678118654752f));
}
__device__ __forceinline__ uint32_t smem_u32(const void* p) {
    uint32_t a;
    asm("{ .reg .u64 t; cvta.to.shared.u64 t, %1; cvt.u32.u64 %0, t; }" : "=r"(a) : "l"(p));
    return a;
}
__device__ __forceinline__ void cp16(__half* dst, const __half* src) {
    asm volatile("cp.async.cg.shared.global [%0], [%1], 16;"
                 :: "r"(smem_u32(dst)), "l"(src));
}
#define CP_COMMIT() asm volatile("cp.async.commit_group;" ::: "memory")
#define CP_WAIT0()  asm volatile("cp.async.wait_group 0;" ::: "memory")

// ---------------- effective relation weights (fp32), widened ------------------
__global__ void build_eff_kernel(const float* __restrict__ Wk, const float* __restrict__ bk,
                                 const float* __restrict__ Wv, const float* __restrict__ bv,
                                 const float* __restrict__ a_rel, const float* __restrict__ m_rel,
                                 float* __restrict__ Weff, float* __restrict__ beff) {
    int b = blockIdx.x;
    int u = b >> 2, chunk = b & 3;
    int l = u / 6, rem = u % 6, r = rem >> 1, kv = rem & 1;
    int st = (r == 1) ? 1 : 0;
    const float* W   = (kv ? Wv : Wk) + (l * 2 + st) * CC * CC;
    const float* bi  = (kv ? bv : bk) + (l * 2 + st) * CC;
    const float* rel = (kv ? m_rel : a_rel) + (l * 3 + r) * 4096;
    float* out  = Weff + ((l * 3 + r) * 2 + kv) * CC * CC;
    float* bout = beff + ((l * 3 + r) * 2 + kv) * CC;

    __shared__ float rs[4096];
    for (int i = threadIdx.x; i < 4096; i += blockDim.x) rs[i] = rel[i];
    __syncthreads();

    int i0 = chunk * 32;
    for (int idx = threadIdx.x; idx < 32 * CC; idx += blockDim.x) {
        int i = i0 + (idx >> 7), j = idx & 127, h = j >> 5, e = j & 31;
        float s = 0.f;
#pragma unroll
        for (int d = 0; d < 32; d++)
            s += W[i * CC + h * 32 + d] * rs[h * 1024 + d * 32 + e];
        out[i * CC + j] = s;
    }
    if (chunk == 0 && threadIdx.x < CC) {
        int j = threadIdx.x, h = j >> 5, e = j & 31;
        float s = 0.f;
#pragma unroll
        for (int d = 0; d < 32; d++)
            s += bi[h * 32 + d] * rs[h * 1024 + d * 32 + e];
        bout[j] = s;
    }
}

// ---------------- weight prep: transpose + fp16 round, widened ----------------
__global__ void prep_wh_kernel(const float* __restrict__ Wq, const float* __restrict__ Wa,
                               const float* __restrict__ Weff, __half* __restrict__ Wh) {
    int b = blockIdx.x;
    int mat = b >> 2, chunk = b & 3;
    int l = mat / 10, m = mat % 10;
    const float* src;
    if (m < 2)       src = Wq + (size_t)(l * 2 + m) * CC * CC;
    else if (m < 8)  src = Weff + (size_t)((l * 3 + (m - 2) / 2) * 2 + ((m - 2) & 1)) * CC * CC;
    else             src = Wa + (size_t)(l * 2 + (m - 8)) * CC * CC;
    __half* out = Wh + (size_t)mat * CC * CC;
    int base = chunk * 4096;
    for (int t = threadIdx.x; t < 4096; t += blockDim.x) {
        int idx = base + t;
        int n = idx >> 7, k = idx & 127;
        out[idx] = __float2half(src[k * CC + n]);   // [n][k] = W[k][n]
    }
}

// ---------------- CSR build ---------------------------------------------------
__global__ void hist_kernel(const int* __restrict__ ei0, const int* __restrict__ ei1,
                            const int* __restrict__ ei2, int* __restrict__ cnt) {
    int t = blockIdx.x * blockDim.x + threadIdx.x;
    if (t >= 3 * EE) return;
    int r = t / EE, e = t - r * EE;
    const int* ei = (r == 0) ? ei0 : ((r == 1) ? ei1 : ei2);
    int dst = ei[EE + e];
    int cb = (r == 0) ? 0 : ((r == 1) ? NN : (NN + NU));
    atomicAdd(&cnt[cb + dst], 1);
}

__global__ void scan1_kernel(const int* __restrict__ cnt, int* __restrict__ offAll,
                             int* __restrict__ bsum) {
    __shared__ int wsum[32];
    int lane = threadIdx.x & 31, wid = threadIdx.x >> 5;
    int base = blockIdx.x * SCAN_BLK + threadIdx.x * 4;
    int v0 = (base + 0 < NDST) ? cnt[base + 0] : 0;
    int v1 = (base + 1 < NDST) ? cnt[base + 1] : 0;
    int v2 = (base + 2 < NDST) ? cnt[base + 2] : 0;
    int v3 = (base + 3 < NDST) ? cnt[base + 3] : 0;
    int tsum = v0 + v1 + v2 + v3;
    int x = tsum;
#pragma unroll
    for (int d = 1; d < 32; d <<= 1) {
        int y = __shfl_up_sync(0xffffffffu, x, d);
        if (lane >= d) x += y;
    }
    if (lane == 31) wsum[wid] = x;
    __syncthreads();
    if (wid == 0) {
        int s = wsum[lane];
#pragma unroll
        for (int d = 1; d < 32; d <<= 1) {
            int y = __shfl_up_sync(0xffffffffu, s, d);
            if (lane >= d) s += y;
        }
        wsum[lane] = s;
    }
    __syncthreads();
    int run = x - tsum + ((wid > 0) ? wsum[wid - 1] : 0);
    if (base + 0 < NDST) offAll[base + 0] = run;  run += v0;
    if (base + 1 < NDST) offAll[base + 1] = run;  run += v1;
    if (base + 2 < NDST) offAll[base + 2] = run;  run += v2;
    if (base + 3 < NDST) offAll[base + 3] = run;
    if (threadIdx.x == 0) bsum[blockIdx.x] = wsum[31];
}

__global__ void scan2_kernel(int* __restrict__ bsum) {
    int lane = threadIdx.x;
    int v = (lane < SCAN_NB) ? bsum[lane] : 0;
    int x = v;
#pragma unroll
    for (int d = 1; d < 32; d <<= 1) {
        int y = __shfl_up_sync(0xffffffffu, x, d);
        if ((lane & 31) >= d) x += y;
    }
    __shared__ int w0tot;
    if (lane == 31) w0tot = x;
    __syncthreads();
    if (lane >= 32) x += w0tot;
    if (lane < SCAN_NB) bsum[lane] = x - v;
}

__global__ void scan3_kernel(int* __restrict__ offAll, const int* __restrict__ bsum) {
    int base = blockIdx.x * SCAN_BLK + threadIdx.x * 4;
    int add = bsum[blockIdx.x];
#pragma unroll
    for (int j = 0; j < 4; j++)
        if (base + j < NDST) offAll[base + j] += add;
    if (blockIdx.x == 0 && threadIdx.x == 0) offAll[NDST] = 3 * EE;
}

__global__ void scatter_kernel(const int* __restrict__ ei0, const int* __restrict__ ei1,
                               const int* __restrict__ ei2,
                               const int* __restrict__ offAll,
                               int* __restrict__ fill, int* __restrict__ srt) {
    int t = blockIdx.x * blockDim.x + threadIdx.x;
    if (t >= 3 * EE) return;
    int r = t / EE, e = t - r * EE;
    const int* ei = (r == 0) ? ei0 : ((r == 1) ? ei1 : ei2);
    int src = ei[e], dst = ei[EE + e];
    int cb = (r == 0) ? 0 : ((r == 1) ? NN : (NN + NU));
    int pos = offAll[cb + dst] + atomicAdd(&fill[cb + dst], 1);
    srt[pos] = src;
}

// ---------------- MMA compute via ldmatrix: 128x128 tile, 8 warps (4m x 2n) --
__device__ __forceinline__ void mma_tile_128(const __half* As, const __half* Bs,
                                             float acc[2][8][4], int wm, int wn,
                                             int lane) {
    int rsel = ((lane >> 3) & 1) * 8 + (lane & 7);
    int csel = (lane >> 4) * 8;
    uint32_t aAddr[2], bAddr[4];
#pragma unroll
    for (int m = 0; m < 2; m++)
        aAddr[m] = smem_u32(As + (size_t)(wm * 32 + m * 16 + rsel) * SA + csel);
    int bksel = ((lane >> 3) & 1) * 8;
    int bnsel = (lane >> 4);
#pragma unroll
    for (int p = 0; p < 4; p++)
        bAddr[p] = smem_u32(Bs + (size_t)(wn * 64 + (2 * p + bnsel) * 8 + (lane & 7)) * SA + bksel);

#pragma unroll
    for (int k0 = 0; k0 < CC; k0 += 16) {
        uint32_t a[2][4];
#pragma unroll
        for (int m = 0; m < 2; m++) {
            asm volatile("ldmatrix.sync.aligned.m8n8.x4.shared.b16 {%0,%1,%2,%3}, [%4];"
                         : "=r"(a[m][0]), "=r"(a[m][1]), "=r"(a[m][2]), "=r"(a[m][3])
                         : "r"(aAddr[m]));
            aAddr[m] += 32;
        }
        uint32_t b[8][2];
#pragma unroll
        for (int p = 0; p < 4; p++) {
            asm volatile("ldmatrix.sync.aligned.m8n8.x4.shared.b16 {%0,%1,%2,%3}, [%4];"
                         : "=r"(b[2 * p][0]), "=r"(b[2 * p][1]),
                           "=r"(b[2 * p + 1][0]), "=r"(b[2 * p + 1][1])
                         : "r"(bAddr[p]));
            bAddr[p] += 32;
        }
#pragma unroll
        for (int m = 0; m < 2; m++)
#pragma unroll
            for (int n = 0; n < 8; n++) {
                float* c = acc[m][n];
                asm volatile(
                    "mma.sync.aligned.m16n8k16.row.col.f32.f16.f16.f32 "
                    "{%0,%1,%2,%3}, {%4,%5,%6,%7}, {%8,%9}, {%0,%1,%2,%3};"
                    : "+f"(c[0]), "+f"(c[1]), "+f"(c[2]), "+f"(c[3])
                    : "r"(a[m][0]), "r"(a[m][1]), "r"(a[m][2]), "r"(a[m][3]),
                      "r"(b[n][0]), "r"(b[n][1]));
            }
    }
}

__device__ __forceinline__ void prefetch_B(__half* Bs, const __half* W, int tid) {
#pragma unroll
    for (int it = 0; it < 8; it++) {
        int c = tid + it * 256;
        int n = c >> 4, cc = c & 15;
        cp16(Bs + n * SA + cc * 8, W + n * CC + cc * 8);
    }
    CP_COMMIT();
}

// ---------------- merged projection kernel (user 5W + news 3W) ---------------
struct ProjArgs {
    const float* XU; const float* XN;
    const __half* XUh; const __half* XNh;
    int useH;
    int gridU;
    const __half* W[8];
    const float* bias[8];
    __half* out[8];
};

__global__ __launch_bounds__(256, 2)
void proj_kernel(ProjArgs pa) {
    extern __shared__ __half smh[];
    __half* As  = smh;
    __half* Bs0 = smh + 128 * SA;
    __half* Bs1 = smh + 2 * 128 * SA;
    int tid = threadIdx.x;

    const float* X;
    const __half* Xh;
    int N, row0, w0, nW;
    if ((int)blockIdx.x < pa.gridU) {
        X = pa.XU; Xh = pa.XUh; N = NU; row0 = blockIdx.x * 128; w0 = 0; nW = 5;
    } else {
        X = pa.XN; Xh = pa.XNh; N = NN; row0 = (blockIdx.x - pa.gridU) * 128; w0 = 5; nW = 3;
    }

    prefetch_B(Bs0, pa.W[w0], tid);

    if (!pa.useH) {
        const float4* X4 = (const float4*)X;
#pragma unroll
        for (int it = 0; it < 16; it++) {
            int idx = tid + it * 256;
            int row = idx >> 5, q4 = idx & 31;
            int gr = row0 + row;
            float4 v = make_float4(0.f, 0.f, 0.f, 0.f);
            if (gr < N) v = X4[gr * 32 + q4];
            __half2 h0 = __floats2half2_rn(v.x, v.y);
            __half2 h1 = __floats2half2_rn(v.z, v.w);
            uint2 u;
            u.x = *(uint32_t*)&h0; u.y = *(uint32_t*)&h1;
            *(uint2*)(As + row * SA + q4 * 4) = u;
        }
    } else {
#pragma unroll
        for (int it = 0; it < 8; it++) {
            int idx = tid + it * 256;
            int row = idx >> 4, h8 = idx & 15;
            int gr = row0 + row;
            if (gr < N)
                cp16(As + row * SA + h8 * 8, (__half*)Xh + (size_t)gr * CC + h8 * 8);
        }
        CP_COMMIT();
    }
    CP_WAIT0();
    __syncthreads();

    int wid = tid >> 5, lane = tid & 31;
    int wm = wid & 3, wn = wid >> 2;
    int g = lane >> 2, t = lane & 3;

    for (int w = 0; w < nW; w++) {
        __half* Bcur = (w & 1) ? Bs1 : Bs0;
        if (w + 1 < nW) prefetch_B((w & 1) ? Bs0 : Bs1, pa.W[w0 + w + 1], tid);

        float acc[2][8][4];
#pragma unroll
        for (int m = 0; m < 2; m++)
#pragma unroll
            for (int n = 0; n < 8; n++)
#pragma unroll
                for (int c = 0; c < 4; c++) acc[m][n][c] = 0.f;

        mma_tile_128(As, Bcur, acc, wm, wn, lane);

        const float* bias = pa.bias[w0 + w];
        __half* out = pa.out[w0 + w];

        __syncthreads();
#pragma unroll
        for (int m = 0; m < 2; m++)
#pragma unroll
            for (int n = 0; n < 8; n++) {
                int col = wn * 64 + n * 8 + 2 * t;
                float bx = bias[col], by = bias[col + 1];
                int r0 = wm * 32 + m * 16 + g;
                __half2 o0 = __floats2half2_rn(acc[m][n][0] + bx, acc[m][n][1] + by);
                *(__half2*)(Bcur + (size_t)r0 * SA + col) = o0;
                __half2 o1 = __floats2half2_rn(acc[m][n][2] + bx, acc[m][n][3] + by);
                *(__half2*)(Bcur + (size_t)(r0 + 8) * SA + col) = o1;
            }
        __syncthreads();
#pragma unroll
        for (int it = 0; it < 8; it++) {
            int idx = tid + it * 256;
            int row = idx >> 4, h8 = idx & 15;
            int gr = row0 + row;
            if (gr < N)
                *(uint4*)&out[(size_t)gr * CC + h8 * 8] = *(const uint4*)(Bcur + row * SA + h8 * 8);
        }

        if (w + 1 < nW) { CP_WAIT0(); __syncthreads(); }
    }
}

// ---------------- CSR aggregation: warp per (relation,dst) node --------------
// 4-edge unrolled inner loop (split k/v arrays, validated layout).
__global__ __launch_bounds__(256)
void agg_kernel(const int* __restrict__ offAll, const int* __restrict__ srt,
                const __half* __restrict__ qh, const __half* __restrict__ krelh,
                const __half* __restrict__ vrelh,
                const float* __restrict__ prel,
                __half* __restrict__ aggrh) {
    int w = (blockIdx.x * blockDim.x + threadIdx.x) >> 5;
    int lane = threadIdx.x & 31;
    if (w >= NDST) return;
    int r, qrow, kbase;
    if (w < NN)            { r = 0; qrow = NU + w;           kbase = 0;       }
    else if (w < NN + NU)  { r = 1; qrow = w - NN;           kbase = NU;      }
    else                   { r = 2; qrow = w - NN - NU;      kbase = NU + NN; }

    int base = offAll[w];
    int deg = offAll[w + 1] - base;
    int h = lane >> 3;
    float pscale = prel[r * 4 + h] * 0.17677669529663689f;

    uint2 qa = *(const uint2*)(qh + (size_t)qrow * CC + lane * 4);
    float2 q0 = __half22float2(*(__half2*)&qa.x), q1 = __half22float2(*(__half2*)&qa.y);

    float a0 = 0.f, a1 = 0.f, a2 = 0.f, a3 = 0.f, den = 0.f;
    const int* sp = srt + base;
    for (int c = 0; c < deg; c += 32) {
        int m = min(32, deg - c);
        int si = (lane < m) ? sp[c + lane] : 0;
        int i = 0;
        for (; i + 3 < m; i += 4) {
            uint2 ka[4], va[4];
#pragma unroll
            for (int j = 0; j < 4; j++) {
                int e = __shfl_sync(0xffffffffu, si, i + j);
                size_t ro = (size_t)(kbase + e) * CC + lane * 4;
                ka[j] = *(const uint2*)(krelh + ro);
                va[j] = *(const uint2*)(vrelh + ro);
            }
            float s[4];
#pragma unroll
            for (int j = 0; j < 4; j++) {
                float2 k0 = __half22float2(*(__half2*)&ka[j].x);
                float2 k1 = __half22float2(*(__half2*)&ka[j].y);
                s[j] = q0.x * k0.x + q0.y * k0.y + q1.x * k1.x + q1.y * k1.y;
            }
#pragma unroll
            for (int d = 1; d <= 4; d <<= 1)
#pragma unroll
                for (int j = 0; j < 4; j++)
                    s[j] += __shfl_xor_sync(0xffffffffu, s[j], d);
#pragma unroll
            for (int j = 0; j < 4; j++) {
                float ex = __expf(s[j] * pscale);
                float2 v0 = __half22float2(*(__half2*)&va[j].x);
                float2 v1 = __half22float2(*(__half2*)&va[j].y);
                a0 = fmaf(ex, v0.x, a0); a1 = fmaf(ex, v0.y, a1);
                a2 = fmaf(ex, v1.x, a2); a3 = fmaf(ex, v1.y, a3);
                den += ex;
            }
        }
        for (; i < m; i++) {
            int e = __shfl_sync(0xffffffffu, si, i);
            size_t ro = (size_t)(kbase + e) * CC + lane * 4;
            uint2 ka = *(const uint2*)(krelh + ro);
            uint2 va = *(const uint2*)(vrelh + ro);
            float2 k0 = __half22float2(*(__half2*)&ka.x);
            float2 k1 = __half22float2(*(__half2*)&ka.y);
            float s = q0.x * k0.x + q0.y * k0.y + q1.x * k1.x + q1.y * k1.y;
            s += __shfl_xor_sync(0xffffffffu, s, 1);
            s += __shfl_xor_sync(0xffffffffu, s, 2);
            s += __shfl_xor_sync(0xffffffffu, s, 4);
            float ex = __expf(s * pscale);
            float2 v0 = __half22float2(*(__half2*)&va.x);
            float2 v1 = __half22float2(*(__half2*)&va.y);
            a0 = fmaf(ex, v0.x, a0); a1 = fmaf(ex, v0.y, a1);
            a2 = fmaf(ex, v1.x, a2); a3 = fmaf(ex, v1.y, a3);
            den += ex;
        }
    }
    float inv = 1.f / (den + 1e-16f);
    __half2 o0 = __floats2half2_rn(a0 * inv, a1 * inv);
    __half2 o1 = __floats2half2_rn(a2 * inv, a3 * inv);
    uint2 u;
    u.x = *(uint32_t*)&o0; u.y = *(uint32_t*)&o1;
    *(uint2*)&aggrh[(size_t)w * CC + lane * 4] = u;
}

// ---------------- merged output GEMM (user + news) ---------------------------
struct OutArgs {
    int gridU;
    const __half* aggU1; const __half* aggU2; const __half* aggN;
    const __half* WU; const __half* WN;
    const float* biasU; const float* biasN;
    float* YU; float* YN;
    __half* YUh; __half* YNh;
    const float* xoldU; const float* xoldN;
    const __half* xoldUh; const __half* xoldNh;
    const float* skipU; const float* skipN;
    int inH, outH;
};

__global__ __launch_bounds__(256, 2)
void out_kernel(OutArgs oa) {
    extern __shared__ __half smh[];
    __half* As = smh;
    __half* Bs = smh + 128 * SA;
    int tid = threadIdx.x;

    const __half *aggA, *aggB;
    const float *bias, *xold, *skipPtr;
    const __half *W, *xoldh;
    float* Y;
    __half* Yh;
    int N, row0;
    if ((int)blockIdx.x < oa.gridU) {
        aggA = oa.aggU1; aggB = oa.aggU2; W = oa.WU; bias = oa.biasU;
        Y = oa.YU; Yh = oa.YUh; xold = oa.xoldU; xoldh = oa.xoldUh;
        skipPtr = oa.skipU; N = NU;
        row0 = blockIdx.x * 128;
    } else {
        aggA = oa.aggN; aggB = nullptr; W = oa.WN; bias = oa.biasN;
        Y = oa.YN; Yh = oa.YNh; xold = oa.xoldN; xoldh = oa.xoldNh;
        skipPtr = oa.skipN; N = NN;
        row0 = (blockIdx.x - oa.gridU) * 128;
    }

    prefetch_B(Bs, W, tid);

    // A-stage: uint4 loads (8 halves/lane), gelu, store to As
#pragma unroll
    for (int it = 0; it < 8; it++) {
        int idx = tid + it * 256;
        int row = idx >> 4, h8 = idx & 15;
        int gr = row0 + row;
        uint4 o = make_uint4(0u, 0u, 0u, 0u);
        if (gr < N) {
            uint4 ua = *(const uint4*)(aggA + (size_t)gr * CC + h8 * 8);
            float2 f0 = __half22float2(*(__half2*)&ua.x);
            float2 f1 = __half22float2(*(__half2*)&ua.y);
            float2 f2 = __half22float2(*(__half2*)&ua.z);
            float2 f3 = __half22float2(*(__half2*)&ua.w);
            if (aggB) {
                uint4 ub = *(const uint4*)(aggB + (size_t)gr * CC + h8 * 8);
                float2 g0 = __half22float2(*(__half2*)&ub.x);
                float2 g1 = __half22float2(*(__half2*)&ub.y);
                float2 g2 = __half22float2(*(__half2*)&ub.z);
                float2 g3 = __half22float2(*(__half2*)&ub.w);
                f0.x += g0.x; f0.y += g0.y; f1.x += g1.x; f1.y += g1.y;
                f2.x += g2.x; f2.y += g2.y; f3.x += g3.x; f3.y += g3.y;
            }
            __half2 h0 = __floats2half2_rn(gelu_exact(f0.x), gelu_exact(f0.y));
            __half2 h1 = __floats2half2_rn(gelu_exact(f1.x), gelu_exact(f1.y));
            __half2 h2 = __floats2half2_rn(gelu_exact(f2.x), gelu_exact(f2.y));
            __half2 h3 = __floats2half2_rn(gelu_exact(f3.x), gelu_exact(f3.y));
            o.x = *(uint32_t*)&h0; o.y = *(uint32_t*)&h1;
            o.z = *(uint32_t*)&h2; o.w = *(uint32_t*)&h3;
        }
        *(uint4*)(As + row * SA + h8 * 8) = o;
    }
    CP_WAIT0();
    __syncthreads();

    int wid = tid >> 5, lane = tid & 31;
    int wm = wid & 3, wn = wid >> 2;
    int g = lane >> 2, t = lane & 3;

    float acc[2][8][4];
#pragma unroll
    for (int m = 0; m < 2; m++)
#pragma unroll
        for (int n = 0; n < 8; n++)
#pragma unroll
            for (int c = 0; c < 4; c++) acc[m][n][c] = 0.f;

    mma_tile_128(As, Bs, acc, wm, wn, lane);

    float s = *skipPtr;
    float aS = 1.f / (1.f + expf(-s));
    float bS = 1.f - aS;

    if (oa.outH) {
        __syncthreads();
#pragma unroll
        for (int m = 0; m < 2; m++)
#pragma unroll
            for (int n = 0; n < 8; n++) {
                int col = wn * 64 + n * 8 + 2 * t;
                float bx = bias[col], by = bias[col + 1];
#pragma unroll
                for (int hrow = 0; hrow < 2; hrow++) {
                    int lr = wm * 32 + m * 16 + hrow * 8 + g;
                    int rr = row0 + lr;
                    float ox = acc[m][n][2 * hrow + 0] + bx;
                    float oy = acc[m][n][2 * hrow + 1] + by;
                    float2 xo = make_float2(0.f, 0.f);
                    if (rr < N) {
                        if (oa.inH) {
                            uint32_t up = *(const uint32_t*)&xoldh[(size_t)rr * CC + col];
                            xo = __half22float2(*(__half2*)&up);
                        } else {
                            xo = *(const float2*)&xold[(size_t)rr * CC + col];
                        }
                    }
                    ox = fmaxf(fmaf(aS, ox, bS * xo.x), 0.f);
                    oy = fmaxf(fmaf(aS, oy, bS * xo.y), 0.f);
                    __half2 oh = __floats2half2_rn(ox, oy);
                    *(__half2*)(Bs + (size_t)lr * SA + col) = oh;
                }
            }
        __syncthreads();
#pragma unroll
        for (int it = 0; it < 8; it++) {
            int idx = tid + it * 256;
            int row = idx >> 4, h8 = idx & 15;
            int gr = row0 + row;
            if (gr < N)
                *(uint4*)&Yh[(size_t)gr * CC + h8 * 8] = *(const uint4*)(Bs + row * SA + h8 * 8);
        }
    } else {
#pragma unroll
        for (int m = 0; m < 2; m++)
#pragma unroll
            for (int n = 0; n < 8; n++) {
                int col = wn * 64 + n * 8 + 2 * t;
                float bx = bias[col], by = bias[col + 1];
#pragma unroll
                for (int hrow = 0; hrow < 2; hrow++) {
                    int rr = row0 + wm * 32 + m * 16 + hrow * 8 + g;
                    if (rr >= N) continue;
                    float ox = acc[m][n][2 * hrow + 0] + bx;
                    float oy = acc[m][n][2 * hrow + 1] + by;
                    float2 xo;
                    if (oa.inH) {
                        uint32_t up = *(const uint32_t*)&xoldh[(size_t)rr * CC + col];
                        xo = __half22float2(*(__half2*)&up);
                    } else {
                        xo = *(const float2*)&xold[(size_t)rr * CC + col];
                    }
                    ox = fmaxf(fmaf(aS, ox, bS * xo.x), 0.f);
                    oy = fmaxf(fmaf(aS, oy, bS * xo.y), 0.f);
                    float2 o2; o2.x = ox; o2.y = oy;
                    *(float2*)&Y[(size_t)rr * CC + col] = o2;
                }
            }
    }
}

// ---------------- host orchestration ----------------------------------------
extern "C" void kernel_launch(void* const* d_in, const int* in_sizes, int n_in,
                              void* d_out, int out_size) {
    const float* x_user = (const float*)d_in[0];
    const float* x_news = (const float*)d_in[1];
    const int* ei0 = (const int*)d_in[2];
    const int* ei1 = (const int*)d_in[3];
    const int* ei2 = (const int*)d_in[4];
    const float* Wk = (const float*)d_in[5];
    const float* bk = (const float*)d_in[6];
    const float* Wq = (const float*)d_in[7];
    const float* bq = (const float*)d_in[8];
    const float* Wv = (const float*)d_in[9];
    const float* bv = (const float*)d_in[10];
    const float* Wa = (const float*)d_in[11];
    const float* ba = (const float*)d_in[12];
    const float* skip = (const float*)d_in[13];
    const float* a_rel = (const float*)d_in[14];
    const float* m_rel = (const float*)d_in[15];
    const float* p_rel = (const float*)d_in[16];

    float *Weff, *beff;
    __half *x1h, *qh, *krelh, *vrelh, *aggrh, *Wh;
    int *cnt, *offAll, *bsum, *srt;
    cudaGetSymbolAddress((void**)&x1h, g_x1h);
    cudaGetSymbolAddress((void**)&qh, g_qh);
    cudaGetSymbolAddress((void**)&krelh, g_krelh);
    cudaGetSymbolAddress((void**)&vrelh, g_vrelh);
    cudaGetSymbolAddress((void**)&aggrh, g_aggrh);
    cudaGetSymbolAddress((void**)&Weff, g_Weff);
    cudaGetSymbolAddress((void**)&beff, g_beff);
    cudaGetSymbolAddress((void**)&Wh, g_Wh);
    cudaGetSymbolAddress((void**)&cnt, g_cnt);
    cudaGetSymbolAddress((void**)&offAll, g_offAll);
    cudaGetSymbolAddress((void**)&bsum, g_bsum);
    cudaGetSymbolAddress((void**)&srt, g_srt);

    const int smemProj = 3 * 128 * SA * 2;
    const int smemOut  = 2 * 128 * SA * 2;
    cudaFuncSetAttribute(proj_kernel, cudaFuncAttributeMaxDynamicSharedMemorySize, smemProj);
    cudaFuncSetAttribute(out_kernel, cudaFuncAttributeMaxDynamicSharedMemorySize, smemOut);

    const int gridU = (NU + 127) / 128;
    const int gridN = (NN + 127) / 128;
    const int aggBlocks = (NDST + 7) / 8;
    const int eb = (3 * EE + 255) / 256;

    build_eff_kernel<<<48, 256, 0, 0>>>(Wk, bk, Wv, bv, a_rel, m_rel, Weff, beff);
    prep_wh_kernel<<<80, 256, 0, 0>>>(Wq, Wa, Weff, Wh);
    cudaMemsetAsync(cnt, 0, NDST * sizeof(int), 0);
    hist_kernel<<<eb, 256, 0, 0>>>(ei0, ei1, ei2, cnt);

    for (int l = 0; l < NLAYER; l++) {
        size_t wl = (size_t)l * 10 * CC * CC;

        ProjArgs pa;
        pa.gridU = gridU;
        if (l == 0) {
            pa.XU = x_user; pa.XN = x_news; pa.XUh = nullptr; pa.XNh = nullptr; pa.useH = 0;
        } else {
            pa.XU = nullptr; pa.XN = nullptr;
            pa.XUh = x1h; pa.XNh = x1h + (size_t)NU * CC; pa.useH = 1;
        }
        pa.W[0] = Wh + wl + 0 * CC * CC;  pa.bias[0] = bq + (l * 2 + 0) * CC;              pa.out[0] = qh;
        pa.W[1] = Wh + wl + 2 * CC * CC;  pa.bias[1] = beff + ((l * 3 + 0) * 2 + 0) * CC;  pa.out[1] = krelh;
        pa.W[2] = Wh + wl + 3 * CC * CC;  pa.bias[2] = beff + ((l * 3 + 0) * 2 + 1) * CC;  pa.out[2] = vrelh;
        pa.W[3] = Wh + wl + 6 * CC * CC;  pa.bias[3] = beff + ((l * 3 + 2) * 2 + 0) * CC;  pa.out[3] = krelh + (size_t)(NU + NN) * CC;
        pa.W[4] = Wh + wl + 7 * CC * CC;  pa.bias[4] = beff + ((l * 3 + 2) * 2 + 1) * CC;  pa.out[4] = vrelh + (size_t)(NU + NN) * CC;
        pa.W[5] = Wh + wl + 1 * CC * CC;  pa.bias[5] = bq + (l * 2 + 1) * CC;              pa.out[5] = qh + (size_t)NU * CC;
        pa.W[6] = Wh + wl + 4 * CC * CC;  pa.bias[6] = beff + ((l * 3 + 1) * 2 + 0) * CC;  pa.out[6] = krelh + (size_t)NU * CC;
        pa.W[7] = Wh + wl + 5 * CC * CC;  pa.bias[7] = beff + ((l * 3 + 1) * 2 + 1) * CC;  pa.out[7] = vrelh + (size_t)NU * CC;
        proj_kernel<<<gridU + gridN, 256, smemProj, 0>>>(pa);

        if (l == 0) {
            scan1_kernel<<<SCAN_NB, 1024, 0, 0>>>(cnt, offAll, bsum);
            scan2_kernel<<<1, 64, 0, 0>>>(bsum);
            scan3_kernel<<<SCAN_NB, 1024, 0, 0>>>(offAll, bsum);
            cudaMemsetAsync(cnt, 0, NDST * sizeof(int), 0);
            scatter_kernel<<<eb, 256, 0, 0>>>(ei0, ei1, ei2, offAll, cnt, srt);
        }

        agg_kernel<<<aggBlocks, 256, 0, 0>>>(offAll, srt, qh, krelh, vrelh,
                                             p_rel + l * 12, aggrh);

        OutArgs oa;
        oa.gridU = gridU;
        oa.aggU1 = aggrh + (size_t)NN * CC;
        oa.aggU2 = aggrh + (size_t)(NN + NU) * CC;
        oa.aggN  = aggrh;
        oa.WU = Wh + wl + 8 * CC * CC;  oa.WN = Wh + wl + 9 * CC * CC;
        oa.biasU = ba + (l * 2 + 0) * CC;  oa.biasN = ba + (l * 2 + 1) * CC;
        oa.skipU = skip + l * 2 + 0;  oa.skipN = skip + l * 2 + 1;
        if (l == 0) {
            oa.YU = nullptr; oa.YN = nullptr;
            oa.YUh = x1h; oa.YNh = x1h + (size_t)NU * CC;
            oa.xoldU = x_user; oa.xoldN = x_news;
            oa.xoldUh = nullptr; oa.xoldNh = nullptr;
            oa.inH = 0; oa.outH = 1;
        } else {
            oa.YU = (float*)d_out; oa.YN = (float*)d_out + (size_t)NU * CC;
            oa.YUh = nullptr; oa.YNh = nullptr;
            oa.xoldU = nullptr; oa.xoldN = nullptr;
            oa.xoldUh = x1h; oa.xoldNh = x1h + (size_t)NU * CC;
            oa.inH = 1; oa.outH = 0;
        }
        out_kernel<<<gridU + gridN, 256, smemOut, 0>>>(oa);
    }
}

// round 15
// speedup vs baseline: 1.1614x; 1.1614x over previous
#include <cuda_runtime.h>
#include <cuda_fp16.h>
#include <math.h>
#include <stdint.h>

#define NU 100000
#define NN 20000
#define NT 120000
#define CC 128
#define EE 250000
#define NLAYER 2
#define NKV 220000   // NU + NN + NU
#define SA 136       // smem row stride in halves
#define NDST (NN + 2 * NU)   // (relation,dst) nodes: r0=NN, r1=NU, r2=NU
#define SCAN_BLK 4096
#define SCAN_NB ((NDST + SCAN_BLK - 1) / SCAN_BLK)

// ---------------- scratch (device globals; no allocations allowed) ----------
__device__ __half g_x1h[NT * CC];      // layer-0 output, fp16
__device__ __half g_qh[NT * CC];
__device__ __half g_krelh[NKV * CC];
__device__ __half g_vrelh[NKV * CC];
__device__ __half g_aggrh[NKV * CC];   // normalized per-relation agg (fp16)
__device__ float g_Weff[12 * CC * CC];
__device__ float g_beff[12 * CC];
__device__ __half g_Wh[20 * CC * CC];  // fp16, transposed [n][k]
// CSR scratch
__device__ int g_cnt[NDST];
__device__ int g_offAll[NDST + 1];
__device__ int g_bsum[SCAN_NB];
__device__ int g_srt[3 * EE];

__device__ __forceinline__ float gelu_exact(float x) {
    return 0.5f * x * (1.0f + erff(x * 0.70710678118654752f));
}
__device__ __forceinline__ uint32_t smem_u32(const void* p) {
    uint32_t a;
    asm("{ .reg .u64 t; cvta.to.shared.u64 t, %1; cvt.u32.u64 %0, t; }" : "=r"(a) : "l"(p));
    return a;
}
__device__ __forceinline__ void cp16(__half* dst, const __half* src) {
    asm volatile("cp.async.cg.shared.global [%0], [%1], 16;"
                 :: "r"(smem_u32(dst)), "l"(src));
}
#define CP_COMMIT() asm volatile("cp.async.commit_group;" ::: "memory")
#define CP_WAIT0()  asm volatile("cp.async.wait_group 0;" ::: "memory")

// ---------------- effective relation weights (fp32), widened ------------------
__global__ void build_eff_kernel(const float* __restrict__ Wk, const float* __restrict__ bk,
                                 const float* __restrict__ Wv, const float* __restrict__ bv,
                                 const float* __restrict__ a_rel, const float* __restrict__ m_rel,
                                 float* __restrict__ Weff, float* __restrict__ beff) {
    int b = blockIdx.x;
    int u = b >> 2, chunk = b & 3;
    int l = u / 6, rem = u % 6, r = rem >> 1, kv = rem & 1;
    int st = (r == 1) ? 1 : 0;
    const float* W   = (kv ? Wv : Wk) + (l * 2 + st) * CC * CC;
    const float* bi  = (kv ? bv : bk) + (l * 2 + st) * CC;
    const float* rel = (kv ? m_rel : a_rel) + (l * 3 + r) * 4096;
    float* out  = Weff + ((l * 3 + r) * 2 + kv) * CC * CC;
    float* bout = beff + ((l * 3 + r) * 2 + kv) * CC;

    __shared__ float rs[4096];
    for (int i = threadIdx.x; i < 4096; i += blockDim.x) rs[i] = rel[i];
    __syncthreads();

    int i0 = chunk * 32;
    for (int idx = threadIdx.x; idx < 32 * CC; idx += blockDim.x) {
        int i = i0 + (idx >> 7), j = idx & 127, h = j >> 5, e = j & 31;
        float s = 0.f;
#pragma unroll
        for (int d = 0; d < 32; d++)
            s += W[i * CC + h * 32 + d] * rs[h * 1024 + d * 32 + e];
        out[i * CC + j] = s;
    }
    if (chunk == 0 && threadIdx.x < CC) {
        int j = threadIdx.x, h = j >> 5, e = j & 31;
        float s = 0.f;
#pragma unroll
        for (int d = 0; d < 32; d++)
            s += bi[h * 32 + d] * rs[h * 1024 + d * 32 + e];
        bout[j] = s;
    }
}

// ---------------- weight prep: transpose + fp16 round, widened ----------------
__global__ void prep_wh_kernel(const float* __restrict__ Wq, const float* __restrict__ Wa,
                               const float* __restrict__ Weff, __half* __restrict__ Wh) {
    int b = blockIdx.x;
    int mat = b >> 2, chunk = b & 3;
    int l = mat / 10, m = mat % 10;
    const float* src;
    if (m < 2)       src = Wq + (size_t)(l * 2 + m) * CC * CC;
    else if (m < 8)  src = Weff + (size_t)((l * 3 + (m - 2) / 2) * 2 + ((m - 2) & 1)) * CC * CC;
    else             src = Wa + (size_t)(l * 2 + (m - 8)) * CC * CC;
    __half* out = Wh + (size_t)mat * CC * CC;
    int base = chunk * 4096;
    for (int t = threadIdx.x; t < 4096; t += blockDim.x) {
        int idx = base + t;
        int n = idx >> 7, k = idx & 127;
        out[idx] = __float2half(src[k * CC + n]);   // [n][k] = W[k][n]
    }
}

// ---------------- CSR build ---------------------------------------------------
__global__ void hist_kernel(const int* __restrict__ ei0, const int* __restrict__ ei1,
                            const int* __restrict__ ei2, int* __restrict__ cnt) {
    int t = blockIdx.x * blockDim.x + threadIdx.x;
    if (t >= 3 * EE) return;
    int r = t / EE, e = t - r * EE;
    const int* ei = (r == 0) ? ei0 : ((r == 1) ? ei1 : ei2);
    int dst = ei[EE + e];
    int cb = (r == 0) ? 0 : ((r == 1) ? NN : (NN + NU));
    atomicAdd(&cnt[cb + dst], 1);
}

__global__ void scan1_kernel(const int* __restrict__ cnt, int* __restrict__ offAll,
                             int* __restrict__ bsum) {
    __shared__ int wsum[32];
    int lane = threadIdx.x & 31, wid = threadIdx.x >> 5;
    int base = blockIdx.x * SCAN_BLK + threadIdx.x * 4;
    int v0 = (base + 0 < NDST) ? cnt[base + 0] : 0;
    int v1 = (base + 1 < NDST) ? cnt[base + 1] : 0;
    int v2 = (base + 2 < NDST) ? cnt[base + 2] : 0;
    int v3 = (base + 3 < NDST) ? cnt[base + 3] : 0;
    int tsum = v0 + v1 + v2 + v3;
    int x = tsum;
#pragma unroll
    for (int d = 1; d < 32; d <<= 1) {
        int y = __shfl_up_sync(0xffffffffu, x, d);
        if (lane >= d) x += y;
    }
    if (lane == 31) wsum[wid] = x;
    __syncthreads();
    if (wid == 0) {
        int s = wsum[lane];
#pragma unroll
        for (int d = 1; d < 32; d <<= 1) {
            int y = __shfl_up_sync(0xffffffffu, s, d);
            if (lane >= d) s += y;
        }
        wsum[lane] = s;
    }
    __syncthreads();
    int run = x - tsum + ((wid > 0) ? wsum[wid - 1] : 0);
    if (base + 0 < NDST) offAll[base + 0] = run;  run += v0;
    if (base + 1 < NDST) offAll[base + 1] = run;  run += v1;
    if (base + 2 < NDST) offAll[base + 2] = run;  run += v2;
    if (base + 3 < NDST) offAll[base + 3] = run;
    if (threadIdx.x == 0) bsum[blockIdx.x] = wsum[31];
}

__global__ void scan2_kernel(int* __restrict__ bsum) {
    int lane = threadIdx.x;
    int v = (lane < SCAN_NB) ? bsum[lane] : 0;
    int x = v;
#pragma unroll
    for (int d = 1; d < 32; d <<= 1) {
        int y = __shfl_up_sync(0xffffffffu, x, d);
        if ((lane & 31) >= d) x += y;
    }
    __shared__ int w0tot;
    if (lane == 31) w0tot = x;
    __syncthreads();
    if (lane >= 32) x += w0tot;
    if (lane < SCAN_NB) bsum[lane] = x - v;
}

__global__ void scan3_kernel(int* __restrict__ offAll, const int* __restrict__ bsum) {
    int base = blockIdx.x * SCAN_BLK + threadIdx.x * 4;
    int add = bsum[blockIdx.x];
#pragma unroll
    for (int j = 0; j < 4; j++)
        if (base + j < NDST) offAll[base + j] += add;
    if (blockIdx.x == 0 && threadIdx.x == 0) offAll[NDST] = 3 * EE;
}

__global__ void scatter_kernel(const int* __restrict__ ei0, const int* __restrict__ ei1,
                               const int* __restrict__ ei2,
                               const int* __restrict__ offAll,
                               int* __restrict__ fill, int* __restrict__ srt) {
    int t = blockIdx.x * blockDim.x + threadIdx.x;
    if (t >= 3 * EE) return;
    int r = t / EE, e = t - r * EE;
    const int* ei = (r == 0) ? ei0 : ((r == 1) ? ei1 : ei2);
    int src = ei[e], dst = ei[EE + e];
    int cb = (r == 0) ? 0 : ((r == 1) ? NN : (NN + NU));
    int pos = offAll[cb + dst] + atomicAdd(&fill[cb + dst], 1);
    srt[pos] = src;
}

// ---------------- MMA compute via ldmatrix: 128x128 tile, 8 warps (4m x 2n) --
__device__ __forceinline__ void mma_tile_128(const __half* As, const __half* Bs,
                                             float acc[2][8][4], int wm, int wn,
                                             int lane) {
    int rsel = ((lane >> 3) & 1) * 8 + (lane & 7);
    int csel = (lane >> 4) * 8;
    uint32_t aAddr[2], bAddr[4];
#pragma unroll
    for (int m = 0; m < 2; m++)
        aAddr[m] = smem_u32(As + (size_t)(wm * 32 + m * 16 + rsel) * SA + csel);
    int bksel = ((lane >> 3) & 1) * 8;
    int bnsel = (lane >> 4);
#pragma unroll
    for (int p = 0; p < 4; p++)
        bAddr[p] = smem_u32(Bs + (size_t)(wn * 64 + (2 * p + bnsel) * 8 + (lane & 7)) * SA + bksel);

#pragma unroll
    for (int k0 = 0; k0 < CC; k0 += 16) {
        uint32_t a[2][4];
#pragma unroll
        for (int m = 0; m < 2; m++) {
            asm volatile("ldmatrix.sync.aligned.m8n8.x4.shared.b16 {%0,%1,%2,%3}, [%4];"
                         : "=r"(a[m][0]), "=r"(a[m][1]), "=r"(a[m][2]), "=r"(a[m][3])
                         : "r"(aAddr[m]));
            aAddr[m] += 32;
        }
        uint32_t b[8][2];
#pragma unroll
        for (int p = 0; p < 4; p++) {
            asm volatile("ldmatrix.sync.aligned.m8n8.x4.shared.b16 {%0,%1,%2,%3}, [%4];"
                         : "=r"(b[2 * p][0]), "=r"(b[2 * p][1]),
                           "=r"(b[2 * p + 1][0]), "=r"(b[2 * p + 1][1])
                         : "r"(bAddr[p]));
            bAddr[p] += 32;
        }
#pragma unroll
        for (int m = 0; m < 2; m++)
#pragma unroll
            for (int n = 0; n < 8; n++) {
                float* c = acc[m][n];
                asm volatile(
                    "mma.sync.aligned.m16n8k16.row.col.f32.f16.f16.f32 "
                    "{%0,%1,%2,%3}, {%4,%5,%6,%7}, {%8,%9}, {%0,%1,%2,%3};"
                    : "+f"(c[0]), "+f"(c[1]), "+f"(c[2]), "+f"(c[3])
                    : "r"(a[m][0]), "r"(a[m][1]), "r"(a[m][2]), "r"(a[m][3]),
                      "r"(b[n][0]), "r"(b[n][1]));
            }
    }
}

__device__ __forceinline__ void prefetch_B(__half* Bs, const __half* W, int tid) {
#pragma unroll
    for (int it = 0; it < 8; it++) {
        int c = tid + it * 256;
        int n = c >> 4, cc = c & 15;
        cp16(Bs + n * SA + cc * 8, W + n * CC + cc * 8);
    }
    CP_COMMIT();
}

// ---------------- merged projection kernel (user 5W + news 3W) ---------------
struct ProjArgs {
    const float* XU; const float* XN;
    const __half* XUh; const __half* XNh;
    int useH;
    int gridU;
    const __half* W[8];
    const float* bias[8];
    __half* out[8];
};

__global__ __launch_bounds__(256, 2)
void proj_kernel(ProjArgs pa) {
    extern __shared__ __half smh[];
    __half* As  = smh;
    __half* Bs0 = smh + 128 * SA;
    __half* Bs1 = smh + 2 * 128 * SA;
    int tid = threadIdx.x;

    const float* X;
    const __half* Xh;
    int N, row0, w0, nW;
    if ((int)blockIdx.x < pa.gridU) {
        X = pa.XU; Xh = pa.XUh; N = NU; row0 = blockIdx.x * 128; w0 = 0; nW = 5;
    } else {
        X = pa.XN; Xh = pa.XNh; N = NN; row0 = (blockIdx.x - pa.gridU) * 128; w0 = 5; nW = 3;
    }

    prefetch_B(Bs0, pa.W[w0], tid);

    if (!pa.useH) {
        const float4* X4 = (const float4*)X;
#pragma unroll
        for (int it = 0; it < 16; it++) {
            int idx = tid + it * 256;
            int row = idx >> 5, q4 = idx & 31;
            int gr = row0 + row;
            float4 v = make_float4(0.f, 0.f, 0.f, 0.f);
            if (gr < N) v = X4[gr * 32 + q4];
            __half2 h0 = __floats2half2_rn(v.x, v.y);
            __half2 h1 = __floats2half2_rn(v.z, v.w);
            uint2 u;
            u.x = *(uint32_t*)&h0; u.y = *(uint32_t*)&h1;
            *(uint2*)(As + row * SA + q4 * 4) = u;
        }
    } else {
#pragma unroll
        for (int it = 0; it < 8; it++) {
            int idx = tid + it * 256;
            int row = idx >> 4, h8 = idx & 15;
            int gr = row0 + row;
            if (gr < N)
                cp16(As + row * SA + h8 * 8, (__half*)Xh + (size_t)gr * CC + h8 * 8);
        }
        CP_COMMIT();
    }
    CP_WAIT0();
    __syncthreads();

    int wid = tid >> 5, lane = tid & 31;
    int wm = wid & 3, wn = wid >> 2;
    int g = lane >> 2, t = lane & 3;

    for (int w = 0; w < nW; w++) {
        __half* Bcur = (w & 1) ? Bs1 : Bs0;
        if (w + 1 < nW) prefetch_B((w & 1) ? Bs0 : Bs1, pa.W[w0 + w + 1], tid);

        float acc[2][8][4];
#pragma unroll
        for (int m = 0; m < 2; m++)
#pragma unroll
            for (int n = 0; n < 8; n++)
#pragma unroll
                for (int c = 0; c < 4; c++) acc[m][n][c] = 0.f;

        mma_tile_128(As, Bcur, acc, wm, wn, lane);

        const float* bias = pa.bias[w0 + w];
        __half* out = pa.out[w0 + w];

        __syncthreads();
#pragma unroll
        for (int m = 0; m < 2; m++)
#pragma unroll
            for (int n = 0; n < 8; n++) {
                int col = wn * 64 + n * 8 + 2 * t;
                float bx = bias[col], by = bias[col + 1];
                int r0 = wm * 32 + m * 16 + g;
                __half2 o0 = __floats2half2_rn(acc[m][n][0] + bx, acc[m][n][1] + by);
                *(__half2*)(Bcur + (size_t)r0 * SA + col) = o0;
                __half2 o1 = __floats2half2_rn(acc[m][n][2] + bx, acc[m][n][3] + by);
                *(__half2*)(Bcur + (size_t)(r0 + 8) * SA + col) = o1;
            }
        __syncthreads();
#pragma unroll
        for (int it = 0; it < 8; it++) {
            int idx = tid + it * 256;
            int row = idx >> 4, h8 = idx & 15;
            int gr = row0 + row;
            if (gr < N)
                *(uint4*)&out[(size_t)gr * CC + h8 * 8] = *(const uint4*)(Bcur + row * SA + h8 * 8);
        }

        if (w + 1 < nW) { CP_WAIT0(); __syncthreads(); }
    }
}

// ---------------- CSR aggregation: warp per (relation,dst) node --------------
// 2-edge ILP inner loop (validated optimum; 4-edge unroll regressed twice).
__global__ __launch_bounds__(256)
void agg_kernel(const int* __restrict__ offAll, const int* __restrict__ srt,
                const __half* __restrict__ qh, const __half* __restrict__ krelh,
                const __half* __restrict__ vrelh,
                const float* __restrict__ prel,
                __half* __restrict__ aggrh) {
    int w = (blockIdx.x * blockDim.x + threadIdx.x) >> 5;
    int lane = threadIdx.x & 31;
    if (w >= NDST) return;
    int r, qrow, kbase;
    if (w < NN)            { r = 0; qrow = NU + w;           kbase = 0;       }
    else if (w < NN + NU)  { r = 1; qrow = w - NN;           kbase = NU;      }
    else                   { r = 2; qrow = w - NN - NU;      kbase = NU + NN; }

    int base = offAll[w];
    int deg = offAll[w + 1] - base;
    int h = lane >> 3;
    float pscale = prel[r * 4 + h] * 0.17677669529663689f;

    uint2 qa = *(const uint2*)(qh + (size_t)qrow * CC + lane * 4);
    float2 q0 = __half22float2(*(__half2*)&qa.x), q1 = __half22float2(*(__half2*)&qa.y);

    float a0 = 0.f, a1 = 0.f, a2 = 0.f, a3 = 0.f, den = 0.f;
    const int* sp = srt + base;
    for (int c = 0; c < deg; c += 32) {
        int m = min(32, deg - c);
        int si = (lane < m) ? sp[c + lane] : 0;
        int i = 0;
        for (; i + 1 < m; i += 2) {
            int s0 = __shfl_sync(0xffffffffu, si, i);
            int s1 = __shfl_sync(0xffffffffu, si, i + 1);
            size_t ro0 = (size_t)(kbase + s0) * CC + lane * 4;
            size_t ro1 = (size_t)(kbase + s1) * CC + lane * 4;
            uint2 ka0 = *(const uint2*)(krelh + ro0);
            uint2 va0 = *(const uint2*)(vrelh + ro0);
            uint2 ka1 = *(const uint2*)(krelh + ro1);
            uint2 va1 = *(const uint2*)(vrelh + ro1);
            float2 k00 = __half22float2(*(__half2*)&ka0.x), k01 = __half22float2(*(__half2*)&ka0.y);
            float2 k10 = __half22float2(*(__half2*)&ka1.x), k11 = __half22float2(*(__half2*)&ka1.y);
            float sA = q0.x * k00.x + q0.y * k00.y + q1.x * k01.x + q1.y * k01.y;
            float sB = q0.x * k10.x + q0.y * k10.y + q1.x * k11.x + q1.y * k11.y;
            sA += __shfl_xor_sync(0xffffffffu, sA, 1);
            sB += __shfl_xor_sync(0xffffffffu, sB, 1);
            sA += __shfl_xor_sync(0xffffffffu, sA, 2);
            sB += __shfl_xor_sync(0xffffffffu, sB, 2);
            sA += __shfl_xor_sync(0xffffffffu, sA, 4);
            sB += __shfl_xor_sync(0xffffffffu, sB, 4);
            float exA = __expf(sA * pscale);
            float exB = __expf(sB * pscale);
            float2 v00 = __half22float2(*(__half2*)&va0.x), v01 = __half22float2(*(__half2*)&va0.y);
            float2 v10 = __half22float2(*(__half2*)&va1.x), v11 = __half22float2(*(__half2*)&va1.y);
            a0 = fmaf(exA, v00.x, fmaf(exB, v10.x, a0));
            a1 = fmaf(exA, v00.y, fmaf(exB, v10.y, a1));
            a2 = fmaf(exA, v01.x, fmaf(exB, v11.x, a2));
            a3 = fmaf(exA, v01.y, fmaf(exB, v11.y, a3));
            den += exA + exB;
        }
        if (i < m) {
            int s0 = __shfl_sync(0xffffffffu, si, i);
            size_t ro0 = (size_t)(kbase + s0) * CC + lane * 4;
            uint2 ka0 = *(const uint2*)(krelh + ro0);
            uint2 va0 = *(const uint2*)(vrelh + ro0);
            float2 k00 = __half22float2(*(__half2*)&ka0.x), k01 = __half22float2(*(__half2*)&ka0.y);
            float sA = q0.x * k00.x + q0.y * k00.y + q1.x * k01.x + q1.y * k01.y;
            sA += __shfl_xor_sync(0xffffffffu, sA, 1);
            sA += __shfl_xor_sync(0xffffffffu, sA, 2);
            sA += __shfl_xor_sync(0xffffffffu, sA, 4);
            float exA = __expf(sA * pscale);
            float2 v00 = __half22float2(*(__half2*)&va0.x), v01 = __half22float2(*(__half2*)&va0.y);
            a0 = fmaf(exA, v00.x, a0);
            a1 = fmaf(exA, v00.y, a1);
            a2 = fmaf(exA, v01.x, a2);
            a3 = fmaf(exA, v01.y, a3);
            den += exA;
        }
    }
    float inv = 1.f / (den + 1e-16f);
    __half2 o0 = __floats2half2_rn(a0 * inv, a1 * inv);
    __half2 o1 = __floats2half2_rn(a2 * inv, a3 * inv);
    uint2 u;
    u.x = *(uint32_t*)&o0; u.y = *(uint32_t*)&o1;
    *(uint2*)&aggrh[(size_t)w * CC + lane * 4] = u;
}

// ---------------- merged output GEMM (user + news) ---------------------------
struct OutArgs {
    int gridU;
    const __half* aggU1; const __half* aggU2; const __half* aggN;
    const __half* WU; const __half* WN;
    const float* biasU; const float* biasN;
    float* YU; float* YN;
    __half* YUh; __half* YNh;
    const float* xoldU; const float* xoldN;
    const __half* xoldUh; const __half* xoldNh;
    const float* skipU; const float* skipN;
    int inH, outH;
};

__global__ __launch_bounds__(256, 2)
void out_kernel(OutArgs oa) {
    extern __shared__ __half smh[];
    __half* As = smh;
    __half* Bs = smh + 128 * SA;
    int tid = threadIdx.x;

    const __half *aggA, *aggB;
    const float *bias, *xold, *skipPtr;
    const __half *W, *xoldh;
    float* Y;
    __half* Yh;
    int N, row0;
    if ((int)blockIdx.x < oa.gridU) {
        aggA = oa.aggU1; aggB = oa.aggU2; W = oa.WU; bias = oa.biasU;
        Y = oa.YU; Yh = oa.YUh; xold = oa.xoldU; xoldh = oa.xoldUh;
        skipPtr = oa.skipU; N = NU;
        row0 = blockIdx.x * 128;
    } else {
        aggA = oa.aggN; aggB = nullptr; W = oa.WN; bias = oa.biasN;
        Y = oa.YN; Yh = oa.YNh; xold = oa.xoldN; xoldh = oa.xoldNh;
        skipPtr = oa.skipN; N = NN;
        row0 = (blockIdx.x - oa.gridU) * 128;
    }

    prefetch_B(Bs, W, tid);

    // A-stage: uint4 loads (8 halves/lane), gelu, store to As
#pragma unroll
    for (int it = 0; it < 8; it++) {
        int idx = tid + it * 256;
        int row = idx >> 4, h8 = idx & 15;
        int gr = row0 + row;
        uint4 o = make_uint4(0u, 0u, 0u, 0u);
        if (gr < N) {
            uint4 ua = *(const uint4*)(aggA + (size_t)gr * CC + h8 * 8);
            float2 f0 = __half22float2(*(__half2*)&ua.x);
            float2 f1 = __half22float2(*(__half2*)&ua.y);
            float2 f2 = __half22float2(*(__half2*)&ua.z);
            float2 f3 = __half22float2(*(__half2*)&ua.w);
            if (aggB) {
                uint4 ub = *(const uint4*)(aggB + (size_t)gr * CC + h8 * 8);
                float2 g0 = __half22float2(*(__half2*)&ub.x);
                float2 g1 = __half22float2(*(__half2*)&ub.y);
                float2 g2 = __half22float2(*(__half2*)&ub.z);
                float2 g3 = __half22float2(*(__half2*)&ub.w);
                f0.x += g0.x; f0.y += g0.y; f1.x += g1.x; f1.y += g1.y;
                f2.x += g2.x; f2.y += g2.y; f3.x += g3.x; f3.y += g3.y;
            }
            __half2 h0 = __floats2half2_rn(gelu_exact(f0.x), gelu_exact(f0.y));
            __half2 h1 = __floats2half2_rn(gelu_exact(f1.x), gelu_exact(f1.y));
            __half2 h2 = __floats2half2_rn(gelu_exact(f2.x), gelu_exact(f2.y));
            __half2 h3 = __floats2half2_rn(gelu_exact(f3.x), gelu_exact(f3.y));
            o.x = *(uint32_t*)&h0; o.y = *(uint32_t*)&h1;
            o.z = *(uint32_t*)&h2; o.w = *(uint32_t*)&h3;
        }
        *(uint4*)(As + row * SA + h8 * 8) = o;
    }
    CP_WAIT0();
    __syncthreads();

    int wid = tid >> 5, lane = tid & 31;
    int wm = wid & 3, wn = wid >> 2;
    int g = lane >> 2, t = lane & 3;

    float acc[2][8][4];
#pragma unroll
    for (int m = 0; m < 2; m++)
#pragma unroll
        for (int n = 0; n < 8; n++)
#pragma unroll
            for (int c = 0; c < 4; c++) acc[m][n][c] = 0.f;

    mma_tile_128(As, Bs, acc, wm, wn, lane);

    float s = *skipPtr;
    float aS = 1.f / (1.f + expf(-s));
    float bS = 1.f - aS;

    if (oa.outH) {
        __syncthreads();
#pragma unroll
        for (int m = 0; m < 2; m++)
#pragma unroll
            for (int n = 0; n < 8; n++) {
                int col = wn * 64 + n * 8 + 2 * t;
                float bx = bias[col], by = bias[col + 1];
#pragma unroll
                for (int hrow = 0; hrow < 2; hrow++) {
                    int lr = wm * 32 + m * 16 + hrow * 8 + g;
                    int rr = row0 + lr;
                    float ox = acc[m][n][2 * hrow + 0] + bx;
                    float oy = acc[m][n][2 * hrow + 1] + by;
                    float2 xo = make_float2(0.f, 0.f);
                    if (rr < N) {
                        if (oa.inH) {
                            uint32_t up = *(const uint32_t*)&xoldh[(size_t)rr * CC + col];
                            xo = __half22float2(*(__half2*)&up);
                        } else {
                            xo = *(const float2*)&xold[(size_t)rr * CC + col];
                        }
                    }
                    ox = fmaxf(fmaf(aS, ox, bS * xo.x), 0.f);
                    oy = fmaxf(fmaf(aS, oy, bS * xo.y), 0.f);
                    __half2 oh = __floats2half2_rn(ox, oy);
                    *(__half2*)(Bs + (size_t)lr * SA + col) = oh;
                }
            }
        __syncthreads();
#pragma unroll
        for (int it = 0; it < 8; it++) {
            int idx = tid + it * 256;
            int row = idx >> 4, h8 = idx & 15;
            int gr = row0 + row;
            if (gr < N)
                *(uint4*)&Yh[(size_t)gr * CC + h8 * 8] = *(const uint4*)(Bs + row * SA + h8 * 8);
        }
    } else {
#pragma unroll
        for (int m = 0; m < 2; m++)
#pragma unroll
            for (int n = 0; n < 8; n++) {
                int col = wn * 64 + n * 8 + 2 * t;
                float bx = bias[col], by = bias[col + 1];
#pragma unroll
                for (int hrow = 0; hrow < 2; hrow++) {
                    int rr = row0 + wm * 32 + m * 16 + hrow * 8 + g;
                    if (rr >= N) continue;
                    float ox = acc[m][n][2 * hrow + 0] + bx;
                    float oy = acc[m][n][2 * hrow + 1] + by;
                    float2 xo;
                    if (oa.inH) {
                        uint32_t up = *(const uint32_t*)&xoldh[(size_t)rr * CC + col];
                        xo = __half22float2(*(__half2*)&up);
                    } else {
                        xo = *(const float2*)&xold[(size_t)rr * CC + col];
                    }
                    ox = fmaxf(fmaf(aS, ox, bS * xo.x), 0.f);
                    oy = fmaxf(fmaf(aS, oy, bS * xo.y), 0.f);
                    float2 o2; o2.x = ox; o2.y = oy;
                    *(float2*)&Y[(size_t)rr * CC + col] = o2;
                }
            }
    }
}

// ---------------- host orchestration ----------------------------------------
extern "C" void kernel_launch(void* const* d_in, const int* in_sizes, int n_in,
                              void* d_out, int out_size) {
    const float* x_user = (const float*)d_in[0];
    const float* x_news = (const float*)d_in[1];
    const int* ei0 = (const int*)d_in[2];
    const int* ei1 = (const int*)d_in[3];
    const int* ei2 = (const int*)d_in[4];
    const float* Wk = (const float*)d_in[5];
    const float* bk = (const float*)d_in[6];
    const float* Wq = (const float*)d_in[7];
    const float* bq = (const float*)d_in[8];
    const float* Wv = (const float*)d_in[9];
    const float* bv = (const float*)d_in[10];
    const float* Wa = (const float*)d_in[11];
    const float* ba = (const float*)d_in[12];
    const float* skip = (const float*)d_in[13];
    const float* a_rel = (const float*)d_in[14];
    const float* m_rel = (const float*)d_in[15];
    const float* p_rel = (const float*)d_in[16];

    float *Weff, *beff;
    __half *x1h, *qh, *krelh, *vrelh, *aggrh, *Wh;
    int *cnt, *offAll, *bsum, *srt;
    cudaGetSymbolAddress((void**)&x1h, g_x1h);
    cudaGetSymbolAddress((void**)&qh, g_qh);
    cudaGetSymbolAddress((void**)&krelh, g_krelh);
    cudaGetSymbolAddress((void**)&vrelh, g_vrelh);
    cudaGetSymbolAddress((void**)&aggrh, g_aggrh);
    cudaGetSymbolAddress((void**)&Weff, g_Weff);
    cudaGetSymbolAddress((void**)&beff, g_beff);
    cudaGetSymbolAddress((void**)&Wh, g_Wh);
    cudaGetSymbolAddress((void**)&cnt, g_cnt);
    cudaGetSymbolAddress((void**)&offAll, g_offAll);
    cudaGetSymbolAddress((void**)&bsum, g_bsum);
    cudaGetSymbolAddress((void**)&srt, g_srt);

    const int smemProj = 3 * 128 * SA * 2;
    const int smemOut  = 2 * 128 * SA * 2;
    cudaFuncSetAttribute(proj_kernel, cudaFuncAttributeMaxDynamicSharedMemorySize, smemProj);
    cudaFuncSetAttribute(out_kernel, cudaFuncAttributeMaxDynamicSharedMemorySize, smemOut);

    const int gridU = (NU + 127) / 128;
    const int gridN = (NN + 127) / 128;
    const int aggBlocks = (NDST + 7) / 8;
    const int eb = (3 * EE + 255) / 256;

    build_eff_kernel<<<48, 256, 0, 0>>>(Wk, bk, Wv, bv, a_rel, m_rel, Weff, beff);
    prep_wh_kernel<<<80, 256, 0, 0>>>(Wq, Wa, Weff, Wh);
    cudaMemsetAsync(cnt, 0, NDST * sizeof(int), 0);
    hist_kernel<<<eb, 256, 0, 0>>>(ei0, ei1, ei2, cnt);

    for (int l = 0; l < NLAYER; l++) {
        size_t wl = (size_t)l * 10 * CC * CC;

        ProjArgs pa;
        pa.gridU = gridU;
        if (l == 0) {
            pa.XU = x_user; pa.XN = x_news; pa.XUh = nullptr; pa.XNh = nullptr; pa.useH = 0;
        } else {
            pa.XU = nullptr; pa.XN = nullptr;
            pa.XUh = x1h; pa.XNh = x1h + (size_t)NU * CC; pa.useH = 1;
        }
        pa.W[0] = Wh + wl + 0 * CC * CC;  pa.bias[0] = bq + (l * 2 + 0) * CC;              pa.out[0] = qh;
        pa.W[1] = Wh + wl + 2 * CC * CC;  pa.bias[1] = beff + ((l * 3 + 0) * 2 + 0) * CC;  pa.out[1] = krelh;
        pa.W[2] = Wh + wl + 3 * CC * CC;  pa.bias[2] = beff + ((l * 3 + 0) * 2 + 1) * CC;  pa.out[2] = vrelh;
        pa.W[3] = Wh + wl + 6 * CC * CC;  pa.bias[3] = beff + ((l * 3 + 2) * 2 + 0) * CC;  pa.out[3] = krelh + (size_t)(NU + NN) * CC;
        pa.W[4] = Wh + wl + 7 * CC * CC;  pa.bias[4] = beff + ((l * 3 + 2) * 2 + 1) * CC;  pa.out[4] = vrelh + (size_t)(NU + NN) * CC;
        pa.W[5] = Wh + wl + 1 * CC * CC;  pa.bias[5] = bq + (l * 2 + 1) * CC;              pa.out[5] = qh + (size_t)NU * CC;
        pa.W[6] = Wh + wl + 4 * CC * CC;  pa.bias[6] = beff + ((l * 3 + 1) * 2 + 0) * CC;  pa.out[6] = krelh + (size_t)NU * CC;
        pa.W[7] = Wh + wl + 5 * CC * CC;  pa.bias[7] = beff + ((l * 3 + 1) * 2 + 1) * CC;  pa.out[7] = vrelh + (size_t)NU * CC;
        proj_kernel<<<gridU + gridN, 256, smemProj, 0>>>(pa);

        if (l == 0) {
            scan1_kernel<<<SCAN_NB, 1024, 0, 0>>>(cnt, offAll, bsum);
            scan2_kernel<<<1, 64, 0, 0>>>(bsum);
            scan3_kernel<<<SCAN_NB, 1024, 0, 0>>>(offAll, bsum);
            cudaMemsetAsync(cnt, 0, NDST * sizeof(int), 0);
            scatter_kernel<<<eb, 256, 0, 0>>>(ei0, ei1, ei2, offAll, cnt, srt);
        }

        agg_kernel<<<aggBlocks, 256, 0, 0>>>(offAll, srt, qh, krelh, vrelh,
                                             p_rel + l * 12, aggrh);

        OutArgs oa;
        oa.gridU = gridU;
        oa.aggU1 = aggrh + (size_t)NN * CC;
        oa.aggU2 = aggrh + (size_t)(NN + NU) * CC;
        oa.aggN  = aggrh;
        oa.WU = Wh + wl + 8 * CC * CC;  oa.WN = Wh + wl + 9 * CC * CC;
        oa.biasU = ba + (l * 2 + 0) * CC;  oa.biasN = ba + (l * 2 + 1) * CC;
        oa.skipU = skip + l * 2 + 0;  oa.skipN = skip + l * 2 + 1;
        if (l == 0) {
            oa.YU = nullptr; oa.YN = nullptr;
            oa.YUh = x1h; oa.YNh = x1h + (size_t)NU * CC;
            oa.xoldU = x_user; oa.xoldN = x_news;
            oa.xoldUh = nullptr; oa.xoldNh = nullptr;
            oa.inH = 0; oa.outH = 1;
        } else {
            oa.YU = (float*)d_out; oa.YN = (float*)d_out + (size_t)NU * CC;
            oa.YUh = nullptr; oa.YNh = nullptr;
            oa.xoldU = nullptr; oa.xoldN = nullptr;
            oa.xoldUh = x1h; oa.xoldNh = x1h + (size_t)NU * CC;
            oa.inH = 1; oa.outH = 0;
        }
        out_kernel<<<gridU + gridN, 256, smemOut, 0>>>(oa);
    }
}